// round 12
// baseline (speedup 1.0000x reference)
#include <cuda_runtime.h>

#define NHID 25
#define NSTEP 20
#define DTV (1.0/60.0)
#define EPSV 1e-4
#define PQV 5.0
#define QVV 200.0
#define QAV 1.0

// Precomputed constants: q0af[25] | c1[20] | c2[20]
__device__ float g_consts[NHID + 2 * NSTEP];

// ---------------------------------------------------------------------------
// Collapsed problem (verified symbolically against the reference):
//   A0^k = [[I,0,k*Af],[0,1,k*dt],[0,0,1]],  SB_k = [k*dt*Af ; dt^2(0.5+k) ; dt]
//   alpha = Af'Q0Af,  q0af = Q0 Af,  Q0 = Lq Lq' + eps I
//   Qf[i][j] = 2( dt^2 alpha (s2[m] - (i+j)s1[m] + ij s0[m]) + Qv dt^2 s0[m] )
//              + (i==j)(2 Qa + eps),   m = max(i,j)
//   s0/s1/s2[c] = suffix sums over r>=c of w_r {1, r, r^2},  w_19 = Pq
//   p[b,c] = (x·q0af) v1[c] + gv p26[c]          (gp never enters p)
//     v1[c]  = 2dt (s1[c] - c s0[c])
//     p26[c] = 2dt ( alpha (s2[c] + (1-c)s1[c] - c s0[c]) + Qv s0[c] )
//   u = -Qf^{-1} p
//   out[b,s] = gp + (s+1)dt gv + sum_{c<=s} dt^2(0.5+s-c) u[c]
//            = gp + gv*c2[s] + (x·q0af)*c1[s]
//
// Setup: ONE WARP, zero block barriers. fp64 assembly via shuffles; lane i
// caches Qf row i in fp64 registers (qrow) for refinement reuse; fp32
// register Gauss-Jordan (shuffle-broadcast) + 2 rounds fp64 refinement.
// ---------------------------------------------------------------------------
__global__ void __launch_bounds__(32) setup_kernel(const float* __restrict__ Af,
                                                   const float* __restrict__ Lq) {
    const unsigned FULL = 0xffffffffu;
    const int lane = threadIdx.x;
    const double dt = DTV, dt2 = DTV * DTV;
    const bool lh = (lane < NHID);
    const bool ls = (lane < NSTEP);

    // ---- Af, g = Lq'Af, q0af = Lq g + eps Af, alpha = g.g + eps Af.Af ----
    double af = lh ? (double)Af[lane] : 0.0;

    double g = 0.0;
#pragma unroll
    for (int j = 0; j < NHID; j++) {
        double aj = __shfl_sync(FULL, af, j);
        double l = lh ? (double)Lq[j * NHID + lane] : 0.0;
        g += l * aj;
    }

    double q0 = 0.0;
#pragma unroll
    for (int i = 0; i < NHID; i++) {
        double gi = __shfl_sync(FULL, g, i);
        double l = lh ? (double)Lq[lane * NHID + i] : 0.0;
        q0 += l * gi;
    }
    q0 += EPSV * af;

    double acc = g * g + EPSV * af * af;
#pragma unroll
    for (int o = 16; o > 0; o >>= 1) acc += __shfl_xor_sync(FULL, acc, o);
    const double alpha = acc;

    // ---- suffix sums (lane < 20) ----
    double s0 = 0, s1 = 0, s2 = 0;
    if (ls) {
        for (int r = lane; r < NSTEP; r++) {
            double w = (r == NSTEP - 1) ? PQV : 1.0;
            s0 += w; s1 += w * r; s2 += w * (double)r * (double)r;
        }
    }

    // ---- RHS vectors ----
    double v1 = 0, p26 = 0;
    if (ls) {
        double c = (double)lane;
        v1  = 2.0 * dt * (s1 - c * s0);
        p26 = 2.0 * dt * (alpha * (s2 + (1.0 - c) * s1 - c * s0) + QVV * s0);
    }

    // ---- build Qf row of lane i: fp64 cache (qrow) + fp32 augmented (rr) ----
    double qrow[NSTEP];
    float rr[2 * NSTEP];
    {
        const double di = (double)lane;
#pragma unroll
        for (int j = 0; j < NSTEP; j++) {
            double sj0 = __shfl_sync(FULL, s0, j);
            double sj1 = __shfl_sync(FULL, s1, j);
            double sj2 = __shfl_sync(FULL, s2, j);
            double m0 = (j > lane) ? sj0 : s0;
            double m1 = (j > lane) ? sj1 : s1;
            double m2 = (j > lane) ? sj2 : s2;
            double dj = (double)j;
            double q = 2.0 * (dt2 * alpha * (m2 - (di + dj) * m1 + di * dj * m0)
                              + QVV * dt2 * m0);
            if (j == lane) q += 2.0 * QAV + EPSV;
            qrow[j] = ls ? q : 0.0;
            rr[j] = ls ? (float)q : 0.0f;
        }
#pragma unroll
        for (int j = 0; j < NSTEP; j++) rr[NSTEP + j] = (j == lane) ? 1.f : 0.f;
    }

    // ---- fp32 Gauss-Jordan (SPD, no pivoting), shuffle-broadcast ----
#pragma unroll
    for (int k = 0; k < NSTEP; k++) {
        float pk = __shfl_sync(FULL, rr[k], k);
        float s = 1.0f / pk;
        float f = rr[k] * s;
        bool isp = (lane == k);
#pragma unroll
        for (int j = 0; j < 2 * NSTEP; j++) {
            float pj = __shfl_sync(FULL, rr[j], k);
            rr[j] = isp ? pj * s : rr[j] - f * pj;
        }
    }
    // rr[NSTEP+j] = inv[lane][j] for lane < NSTEP

    // ---- y = inv * rhs ----
    double y1 = 0, y2 = 0;
#pragma unroll
    for (int j = 0; j < NSTEP; j++) {
        double vj = __shfl_sync(FULL, v1, j);
        double pj = __shfl_sync(FULL, p26, j);
        double R = (double)rr[NSTEP + j];
        y1 += R * vj;
        y2 += R * pj;
    }

    // ---- 2 rounds fp64 iterative refinement (Qf row cached in qrow) ----
#pragma unroll
    for (int it = 0; it < 2; it++) {
        double a = 0, c = 0;
#pragma unroll
        for (int j = 0; j < NSTEP; j++) {
            double yj1 = __shfl_sync(FULL, y1, j);
            double yj2 = __shfl_sync(FULL, y2, j);
            a += qrow[j] * yj1;
            c += qrow[j] * yj2;
        }
        double res1 = v1 - a, res2 = p26 - c;
        double d1 = 0, d2 = 0;
#pragma unroll
        for (int j = 0; j < NSTEP; j++) {
            double rj1 = __shfl_sync(FULL, res1, j);
            double rj2 = __shfl_sync(FULL, res2, j);
            double R = (double)rr[NSTEP + j];
            d1 += R * rj1;
            d2 += R * rj2;
        }
        y1 += d1;
        y2 += d2;
    }

    // ---- epilogue ----
    double a = 0, b = 0;
#pragma unroll
    for (int c = 0; c < NSTEP; c++) {
        double yc1 = __shfl_sync(FULL, y1, c);
        double yc2 = __shfl_sync(FULL, y2, c);
        if (c <= lane) {
            double ss = dt2 * (0.5 + (double)(lane - c));
            a += ss * yc1;
            b += ss * yc2;
        }
    }
    if (ls) {
        g_consts[NHID + lane]         = (float)(-a);
        g_consts[NHID + NSTEP + lane] = (float)((double)(lane + 1) * dt - b);
    }
    if (lh) g_consts[lane] = (float)q0;
    // Implicit end-of-kernel PDL trigger: dependent grid's
    // cudaGridDependencySynchronize() observes all writes above.
}

// ---------------------------------------------------------------------------
// Main streaming kernel (PDL secondary, also correct as plain launch):
//   out[b,s] = gp[b] + gv[b]*c2[s] + dot(x[b],q0af)*c1[s]
// Phase 1 (independent of setup): stage x via float4 into smem, load gp/gv.
// Then cudaGridDependencySynchronize() -> read g_consts -> dot -> stage the
// per-row triple (dp, gp, gv) -> compute outputs inside the coalesced
// float4 store loop. Stride-25 smem reads are bank-conflict-free (25 coprime
// with 32); the triple reads in the store loop are smem broadcasts.
// ---------------------------------------------------------------------------
__global__ void __launch_bounds__(256) main_kernel(const float* __restrict__ x,
                                                   const float* __restrict__ gp,
                                                   const float* __restrict__ gv,
                                                   float* __restrict__ out) {
    __shared__ float sx[256 * NHID];            // 25.6 KB; head reused for dp/p/v
    __shared__ float sc[NHID + 2 * NSTEP];
    const int t = threadIdx.x;
    const int base = blockIdx.x * 256;

    // Phase 1: coalesced float4 load of 256x25 x-chunk (1600 float4) + gp/gv.
    // base*NHID*4 bytes = blockIdx*25600 — 16B aligned.
    const float4* xb4 = (const float4*)(x + (size_t)base * NHID);
    float4* sx4 = (float4*)sx;
#pragma unroll
    for (int k = 0; k < 6; k++) sx4[k * 256 + t] = xb4[k * 256 + t];
    if (t < 64) sx4[1536 + t] = xb4[1536 + t];
    const float p = gp[base + t];
    const float v = gv[base + t];

    // Wait for setup_kernel's writes to g_consts (no-op if launched plain).
    cudaGridDependencySynchronize();

    if (t < NHID + 2 * NSTEP) sc[t] = g_consts[t];
    __syncthreads();

    float dp = 0.f;
#pragma unroll
    for (int i = 0; i < NHID; i++) dp = fmaf(sx[t * NHID + i], sc[i], dp);

    __syncthreads();   // x consumed; reuse smem head for per-row (dp, p, v)
    sx[t] = dp;
    sx[256 + t] = p;
    sx[512 + t] = v;
    __syncthreads();

    // Coalesced float4 store of 256x20 output (1280 float4, 5 per thread).
    // 20 % 4 == 0 -> each float4 lies in one batch row r.
    float4* ob4 = (float4*)(out + (size_t)base * NSTEP);
#pragma unroll
    for (int k = 0; k < 5; k++) {
        int j4 = k * 256 + t;
        int j = 4 * j4;
        int r = j / NSTEP;
        int c = j - r * NSTEP;
        float dpr = sx[r];
        float pr  = sx[256 + r];
        float vr  = sx[512 + r];
        float4 vv;
        vv.x = fmaf(vr, sc[NHID + NSTEP + c    ], fmaf(dpr, sc[NHID + c    ], pr));
        vv.y = fmaf(vr, sc[NHID + NSTEP + c + 1], fmaf(dpr, sc[NHID + c + 1], pr));
        vv.z = fmaf(vr, sc[NHID + NSTEP + c + 2], fmaf(dpr, sc[NHID + c + 2], pr));
        vv.w = fmaf(vr, sc[NHID + NSTEP + c + 3], fmaf(dpr, sc[NHID + c + 3], pr));
        ob4[j4] = vv;
    }
}

extern "C" void kernel_launch(void* const* d_in, const int* in_sizes, int n_in,
                              void* d_out, int out_size) {
    const float* x  = (const float*)d_in[0];
    const float* gp = (const float*)d_in[1];
    const float* gv = (const float*)d_in[2];
    const float* Af = (const float*)d_in[3];
    const float* Lq = (const float*)d_in[4];
    float* out = (float*)d_out;

    // Batch from the output size: out is [B, NSTEP]. Robust to input order.
    const int nB = out_size / NSTEP;

    setup_kernel<<<1, 32>>>(Af, Lq);

    // Programmatic dependent launch (sm_90+ feature; GB300 is sm_103a so
    // unconditionally supported): main's blocks start while setup runs;
    // cudaGridDependencySynchronize() gates the g_consts read. Checked
    // fallback to a plain launch as insurance (same kernel body is correct
    // either way — the grid-dependency sync is then trivially satisfied).
    cudaLaunchConfig_t cfg = {};
    cfg.gridDim  = dim3((unsigned)(nB / 256), 1, 1);
    cfg.blockDim = dim3(256, 1, 1);
    cfg.dynamicSmemBytes = 0;
    cfg.stream = 0;
    cudaLaunchAttribute attr[1];
    attr[0].id = cudaLaunchAttributeProgrammaticStreamSerialization;
    attr[0].val.programmaticStreamSerializationAllowed = 1;
    cfg.attrs = attr;
    cfg.numAttrs = 1;
    cudaError_t err = cudaLaunchKernelEx(&cfg, main_kernel, x, gp, gv, out);
    if (err != cudaSuccess) {
        (void)cudaGetLastError();   // clear sticky error, plain launch
        main_kernel<<<nB / 256, 256>>>(x, gp, gv, out);
    }
}

// round 14
// speedup vs baseline: 1.5042x; 1.5042x over previous
#include <cuda_runtime.h>

#define NHID 25
#define NSTEP 20
#define DTV (1.0/60.0)
#define DTF 0.016666666666666666f
#define EPSV 1e-4f
#define PQV 5.0f
#define QVV 200.0f
#define QAV 1.0f

// Precomputed constants: q0af[25] | c1[20] | c2[20]
__device__ float g_consts[NHID + 2 * NSTEP];

// ---------------------------------------------------------------------------
// Collapsed problem: out[b,s] = gp + gv*c2[s] + (x·q0af)*c1[s]
//   q0af = Q0 Af, alpha = Af'Q0Af, Q0 = Lq Lq' + eps I
//   Qf[i][j] = 2( dt^2 alpha (s2[m] - (i+j)s1[m] + ij s0[m]) + Qv dt^2 s0[m] )
//              + (i==j)(2 Qa + eps),  m = max(i,j); s* = suffix sums (w_19=Pq)
//   v1[c]  = 2dt (s1[c] - c s0[c]);  p26[c] = 2dt(alpha(s2[c]+(1-c)s1[c]-c s0[c]) + Qv s0[c])
//   y = Qf^{-1} {v1, p26};  c1[s] = -sum_{c<=s} dt^2(0.5+s-c) y1[c];
//   c2[s] = (s+1)dt - sum_{c<=s} dt^2(0.5+s-c) y2[c]
//
// Setup: ONE WARP, fp32 throughout (s-sums are integer-exact in fp32) +
// fp64 Qf rows cached for ONE fp64 iterative-refinement round after the
// fp32 shuffle-broadcast Gauss-Jordan. Round-12 profile showed the previous
// fp64-heavy version cost ~31us; this cuts the DFMA dependency chains ~6x.
// ---------------------------------------------------------------------------
__global__ void __launch_bounds__(32) setup_kernel(const float* __restrict__ Af,
                                                   const float* __restrict__ Lq) {
    const unsigned FULL = 0xffffffffu;
    const int lane = threadIdx.x;
    const float dtf = DTF, dt2f = DTF * DTF;
    const bool lh = (lane < NHID);
    const bool ls = (lane < NSTEP);

    // ---- fp32 assembly: g = Lq'Af, q0af = Lq g + eps Af, alpha ----
    float af = lh ? Af[lane] : 0.0f;

    float g = 0.0f;
#pragma unroll
    for (int j = 0; j < NHID; j++) {
        float aj = __shfl_sync(FULL, af, j);
        float l = lh ? Lq[j * NHID + lane] : 0.0f;
        g = fmaf(l, aj, g);
    }

    float q0 = 0.0f;
#pragma unroll
    for (int i = 0; i < NHID; i++) {
        float gi = __shfl_sync(FULL, g, i);
        float l = lh ? Lq[lane * NHID + i] : 0.0f;
        q0 = fmaf(l, gi, q0);
    }
    q0 = fmaf(EPSV, af, q0);

    float acc = fmaf(g, g, EPSV * af * af);
#pragma unroll
    for (int o = 16; o > 0; o >>= 1) acc += __shfl_xor_sync(FULL, acc, o);
    const float alpha = acc;
    const double dalpha = (double)alpha;

    // ---- suffix sums (integer-valued -> exact in fp32) ----
    float s0 = 0, s1 = 0, s2 = 0;
    if (ls) {
        for (int r = lane; r < NSTEP; r++) {
            float w = (r == NSTEP - 1) ? PQV : 1.0f;
            s0 += w; s1 += w * r; s2 += w * (float)(r * r);
        }
    }

    // ---- RHS vectors (fp32) ----
    float v1 = 0, p26 = 0;
    if (ls) {
        float c = (float)lane;
        v1  = 2.0f * dtf * (s1 - c * s0);
        p26 = 2.0f * dtf * (alpha * (s2 + (1.0f - c) * s1 - c * s0) + QVV * s0);
    }

    // ---- Qf row of lane i: fp64 cache (qrow) + fp32 augmented (rr) ----
    double qrow[NSTEP];
    float rr[2 * NSTEP];
    {
        const double di = (double)lane;
        const double dt2d = DTV * DTV;
#pragma unroll
        for (int j = 0; j < NSTEP; j++) {
            float sj0 = __shfl_sync(FULL, s0, j);
            float sj1 = __shfl_sync(FULL, s1, j);
            float sj2 = __shfl_sync(FULL, s2, j);
            double m0 = (double)((j > lane) ? sj0 : s0);
            double m1 = (double)((j > lane) ? sj1 : s1);
            double m2 = (double)((j > lane) ? sj2 : s2);
            double dj = (double)j;
            double q = 2.0 * (dt2d * dalpha * (m2 - (di + dj) * m1 + di * dj * m0)
                              + (double)QVV * dt2d * m0);
            if (j == lane) q += 2.0 * (double)QAV + (double)EPSV;
            qrow[j] = ls ? q : 0.0;
            rr[j] = ls ? (float)q : 0.0f;
        }
#pragma unroll
        for (int j = 0; j < NSTEP; j++) rr[NSTEP + j] = (j == lane) ? 1.f : 0.f;
    }

    // ---- fp32 Gauss-Jordan (SPD, no pivoting), shuffle-broadcast ----
#pragma unroll
    for (int k = 0; k < NSTEP; k++) {
        float pk = __shfl_sync(FULL, rr[k], k);
        float s = 1.0f / pk;
        float f = rr[k] * s;
        bool isp = (lane == k);
#pragma unroll
        for (int j = 0; j < 2 * NSTEP; j++) {
            float pj = __shfl_sync(FULL, rr[j], k);
            rr[j] = isp ? pj * s : rr[j] - f * pj;
        }
    }
    // rr[NSTEP+j] = inv[lane][j] for lane < NSTEP

    // ---- y = inv * rhs (fp32 chains, lat 4) ----
    float y1f = 0, y2f = 0;
#pragma unroll
    for (int j = 0; j < NSTEP; j++) {
        float vj = __shfl_sync(FULL, v1, j);
        float pj = __shfl_sync(FULL, p26, j);
        float R = rr[NSTEP + j];
        y1f = fmaf(R, vj, y1f);
        y2f = fmaf(R, pj, y2f);
    }
    double y1 = (double)y1f, y2 = (double)y2f;

    // ---- ONE fp64 refinement round (kills the kappa*eps fp32 solve error) ----
    {
        double a = 0, c = 0;
#pragma unroll
        for (int j = 0; j < NSTEP; j++) {
            double yj1 = __shfl_sync(FULL, y1, j);
            double yj2 = __shfl_sync(FULL, y2, j);
            a += qrow[j] * yj1;
            c += qrow[j] * yj2;
        }
        double res1 = (double)v1 - a, res2 = (double)p26 - c;
        double d1 = 0, d2 = 0;
#pragma unroll
        for (int j = 0; j < NSTEP; j++) {
            double rj1 = __shfl_sync(FULL, res1, j);
            double rj2 = __shfl_sync(FULL, res2, j);
            double R = (double)rr[NSTEP + j];
            d1 += R * rj1;
            d2 += R * rj2;
        }
        y1 += d1;
        y2 += d2;
    }

    // ---- epilogue in fp32 (short triangular sums) ----
    float z1 = (float)y1, z2 = (float)y2;
    float a = 0, b = 0;
#pragma unroll
    for (int c = 0; c < NSTEP; c++) {
        float zc1 = __shfl_sync(FULL, z1, c);
        float zc2 = __shfl_sync(FULL, z2, c);
        if (c <= lane) {
            float ss = dt2f * (0.5f + (float)(lane - c));
            a = fmaf(ss, zc1, a);
            b = fmaf(ss, zc2, b);
        }
    }
    if (ls) {
        g_consts[NHID + lane]         = -a;
        g_consts[NHID + NSTEP + lane] = (float)(lane + 1) * dtf - b;
    }
    if (lh) g_consts[lane] = q0;
    // Implicit end-of-kernel PDL trigger releases the dependent grid.
}

// ---------------------------------------------------------------------------
// Main streaming kernel — WARP-AUTONOMOUS (round-12 profile: issue 16.6%,
// occ 40.1%, all mem pipes <26% -> latency/barrier bound, 3.46-wave tail).
// Block=128 (4 warps), grid=nB/128=1024 -> 6.92 waves, 99% tail utilization.
// Each warp stages/computes/stores ONLY its own 32 rows; __syncwarp() only,
// zero __syncthreads. Per-warp smem const copies remove cross-warp coupling.
// ---------------------------------------------------------------------------
__global__ void __launch_bounds__(128) main_kernel(const float* __restrict__ x,
                                                   const float* __restrict__ gp,
                                                   const float* __restrict__ gv,
                                                   float* __restrict__ out) {
    __shared__ float sx[128 * NHID];      // 12.8 KB; warp w owns floats [w*800, w*800+800)
    __shared__ float strip[3 * 128];      // dp | p | v per row
    __shared__ float scw[4][80];          // per-warp consts: [0..24]=q0af [25..44]=c1 [45..64]=c2
    const int t = threadIdx.x;
    const int w = t >> 5;
    const int lane = t & 31;
    const int base = blockIdx.x * 128;

    // Phase 1 (independent of setup): warp-local float4 stage of x rows.
    // Warp w rows [32w,32w+32): 3200 B = 200 float4 at block-slice offset 200w.
    const float4* xb4 = (const float4*)(x + (size_t)base * NHID);
    float4* sx4 = (float4*)sx;
#pragma unroll
    for (int k = 0; k < 7; k++) {
        int i = k * 32 + lane;
        if (i < 200) {
            int idx = w * 200 + i;
            sx4[idx] = xb4[idx];
        }
    }
    const float p = gp[base + t];
    const float v = gv[base + t];

    // Gate on setup_kernel's g_consts (no-op when launched plain).
    cudaGridDependencySynchronize();

    // Per-warp constant copy (no block barrier needed).
#pragma unroll
    for (int k = 0; k < 3; k++) {
        int i = k * 32 + lane;
        if (i < NHID + 2 * NSTEP) scw[w][i] = g_consts[i];
    }
    __syncwarp();

    // Dot: stride-25 smem reads, conflict-free (25 coprime 32); consts broadcast.
    float dp = 0.f;
#pragma unroll
    for (int i = 0; i < NHID; i++) dp = fmaf(sx[t * NHID + i], scw[w][i], dp);

    strip[t] = dp;
    strip[128 + t] = p;
    strip[256 + t] = v;
    __syncwarp();

    // Warp-local coalesced float4 store: warp w writes float4s [160w,160w+160).
    // 20 % 4 == 0 -> each float4 lies in one row r in [32w, 32w+32).
    float4* ob4 = (float4*)(out + (size_t)base * NSTEP);
#pragma unroll
    for (int k = 0; k < 5; k++) {
        int j4 = w * 160 + k * 32 + lane;
        int j = 4 * j4;
        int r = j / NSTEP;
        int c = j - r * NSTEP;
        float dpr = strip[r];
        float pr  = strip[128 + r];
        float vr  = strip[256 + r];
        float4 vv;
        vv.x = fmaf(vr, scw[w][NHID + NSTEP + c    ], fmaf(dpr, scw[w][NHID + c    ], pr));
        vv.y = fmaf(vr, scw[w][NHID + NSTEP + c + 1], fmaf(dpr, scw[w][NHID + c + 1], pr));
        vv.z = fmaf(vr, scw[w][NHID + NSTEP + c + 2], fmaf(dpr, scw[w][NHID + c + 2], pr));
        vv.w = fmaf(vr, scw[w][NHID + NSTEP + c + 3], fmaf(dpr, scw[w][NHID + c + 3], pr));
        ob4[j4] = vv;
    }
}

extern "C" void kernel_launch(void* const* d_in, const int* in_sizes, int n_in,
                              void* d_out, int out_size) {
    const float* x  = (const float*)d_in[0];
    const float* gp = (const float*)d_in[1];
    const float* gv = (const float*)d_in[2];
    const float* Af = (const float*)d_in[3];
    const float* Lq = (const float*)d_in[4];
    float* out = (float*)d_out;

    const int nB = out_size / NSTEP;     // out is [B, NSTEP]

    setup_kernel<<<1, 32>>>(Af, Lq);

    // PDL: main's blocks start while setup runs; the grid-dependency sync
    // inside gates the g_consts read. Checked fallback to a plain launch.
    cudaLaunchConfig_t cfg = {};
    cfg.gridDim  = dim3((unsigned)(nB / 128), 1, 1);
    cfg.blockDim = dim3(128, 1, 1);
    cfg.dynamicSmemBytes = 0;
    cfg.stream = 0;
    cudaLaunchAttribute attr[1];
    attr[0].id = cudaLaunchAttributeProgrammaticStreamSerialization;
    attr[0].val.programmaticStreamSerializationAllowed = 1;
    cfg.attrs = attr;
    cfg.numAttrs = 1;
    cudaError_t err = cudaLaunchKernelEx(&cfg, main_kernel, x, gp, gv, out);
    if (err != cudaSuccess) {
        (void)cudaGetLastError();
        main_kernel<<<nB / 128, 128>>>(x, gp, gv, out);
    }
}

// round 16
// speedup vs baseline: 1.9238x; 1.2790x over previous
#include <cuda_runtime.h>

#define NHID 25
#define NSTEP 20
#define DTV (1.0/60.0)
#define DTF 0.016666666666666666f
#define EPSV 1e-4f
#define PQV 5.0f
#define QVV 200.0f
#define QAV 1.0f

// Precomputed constants: q0af[25] | c1[20] | c2[20]
__device__ float g_consts[NHID + 2 * NSTEP];

// ---------------------------------------------------------------------------
// Collapsed problem: out[b,s] = gp + gv*c2[s] + (x·q0af)*c1[s]
// (see prior rounds for the derivation; rel_err 6.6e-7 measured)
//
// Setup: ONE WARP. R14 post-mortem: setup+overhead ~18us, dominated by the
// 40-col GJ and two serial 20-deep DFMA chains. This version:
//  - in-place compact Gauss-Jordan (20 cols, hand-verified update rule)
//  - integer parts of Qf computed EXACTLY in fp32 (all ints < 2^24)
//  - fp64 refinement with 4-way split accumulator chains (940 -> ~235 cyc)
// ---------------------------------------------------------------------------
__global__ void __launch_bounds__(32) setup_kernel(const float* __restrict__ Af,
                                                   const float* __restrict__ Lq) {
    const unsigned FULL = 0xffffffffu;
    const int lane = threadIdx.x;
    const float dtf = DTF, dt2f = DTF * DTF;
    const bool lh = (lane < NHID);
    const bool ls = (lane < NSTEP);

    // ---- fp32 assembly: g = Lq'Af, q0af = Lq g + eps Af, alpha ----
    float af = lh ? Af[lane] : 0.0f;

    float g0 = 0.0f, g1 = 0.0f;
#pragma unroll
    for (int j = 0; j < NHID - 1; j += 2) {
        float aj0 = __shfl_sync(FULL, af, j);
        float aj1 = __shfl_sync(FULL, af, j + 1);
        float l0 = lh ? Lq[j * NHID + lane] : 0.0f;
        float l1 = lh ? Lq[(j + 1) * NHID + lane] : 0.0f;
        g0 = fmaf(l0, aj0, g0);
        g1 = fmaf(l1, aj1, g1);
    }
    {
        float aj = __shfl_sync(FULL, af, NHID - 1);
        float l = lh ? Lq[(NHID - 1) * NHID + lane] : 0.0f;
        g0 = fmaf(l, aj, g0);
    }
    float g = g0 + g1;

    float q0a = 0.0f, q0b = 0.0f;
#pragma unroll
    for (int i = 0; i < NHID - 1; i += 2) {
        float gi0 = __shfl_sync(FULL, g, i);
        float gi1 = __shfl_sync(FULL, g, i + 1);
        float l0 = lh ? Lq[lane * NHID + i] : 0.0f;
        float l1 = lh ? Lq[lane * NHID + i + 1] : 0.0f;
        q0a = fmaf(l0, gi0, q0a);
        q0b = fmaf(l1, gi1, q0b);
    }
    {
        float gi = __shfl_sync(FULL, g, NHID - 1);
        float l = lh ? Lq[lane * NHID + NHID - 1] : 0.0f;
        q0a = fmaf(l, gi, q0a);
    }
    float q0 = fmaf(EPSV, af, q0a + q0b);

    float acc = fmaf(g, g, EPSV * af * af);
#pragma unroll
    for (int o = 16; o > 0; o >>= 1) acc += __shfl_xor_sync(FULL, acc, o);
    const float alpha = acc;
    const double dalpha = (double)alpha;

    // ---- suffix sums (integer-valued -> exact in fp32) ----
    float s0 = 0, s1 = 0, s2 = 0;
    if (ls) {
        for (int r = lane; r < NSTEP; r++) {
            float w = (r == NSTEP - 1) ? PQV : 1.0f;
            s0 += w; s1 += w * r; s2 += w * (float)(r * r);
        }
    }

    // ---- RHS vectors (fp32) ----
    float v1 = 0, p26 = 0;
    if (ls) {
        float c = (float)lane;
        v1  = 2.0f * dtf * (s1 - c * s0);
        p26 = 2.0f * dtf * (alpha * (s2 + (1.0f - c) * s1 - c * s0) + QVV * s0);
    }

    // ---- Qf row of lane i: fp64 cache (qrow) + fp32 working copy (rr) ----
    // C_ij = m2 - (i+j)m1 + ij*m0 is integer-exact in fp32 (all < 2^24).
    double qrow[NSTEP];
    float rr[NSTEP];
    {
        const double dt2d = DTV * DTV;
        const double sA = 2.0 * dt2d * dalpha;
        const double sB = 2.0 * (double)QVV * dt2d;
#pragma unroll
        for (int j = 0; j < NSTEP; j++) {
            float sj0 = __shfl_sync(FULL, s0, j);
            float sj1 = __shfl_sync(FULL, s1, j);
            float sj2 = __shfl_sync(FULL, s2, j);
            float m0 = (j > lane) ? sj0 : s0;
            float m1 = (j > lane) ? sj1 : s1;
            float m2 = (j > lane) ? sj2 : s2;
            float C = m2 - (float)(lane + j) * m1 + (float)(lane * j) * m0; // exact
            double q = sA * (double)C + sB * (double)m0;
            if (j == lane) q += 2.0 * (double)QAV + (double)EPSV;
            qrow[j] = ls ? q : 0.0;
            rr[j] = ls ? (float)q : 0.0f;
        }
    }

    // ---- In-place compact Gauss-Jordan inversion (SPD, no pivoting) ----
    // Lane i holds row i. Per step k:
    //   d = 1/A[k][k];  t = A[i][k] (local)
    //   for j: pj = shfl(A[*][j], k); pjd = pj*d
    //          lane k:  A[k][j] = pjd
    //          others:  A[i][j] -= t*pjd
    //   then   lane k:  A[k][k] = d ;  others: A[i][k] = -t*d
#pragma unroll
    for (int k = 0; k < NSTEP; k++) {
        float pk = __shfl_sync(FULL, rr[k], k);
        float d = 1.0f / pk;
        float t = rr[k];
        bool isp = (lane == k);
#pragma unroll
        for (int j = 0; j < NSTEP; j++) {
            float pj = __shfl_sync(FULL, rr[j], k);
            float pjd = pj * d;
            rr[j] = isp ? pjd : fmaf(-t, pjd, rr[j]);
        }
        rr[k] = isp ? d : -t * d;
    }
    // rr[j] now = inv[lane][j] for lane < NSTEP

    // ---- y = inv * rhs (fp32, 2-way split chains) ----
    float ya0 = 0, ya1 = 0, yb0 = 0, yb1 = 0;
#pragma unroll
    for (int j = 0; j < NSTEP; j += 2) {
        float vj0 = __shfl_sync(FULL, v1, j);
        float vj1 = __shfl_sync(FULL, v1, j + 1);
        float pj0 = __shfl_sync(FULL, p26, j);
        float pj1 = __shfl_sync(FULL, p26, j + 1);
        ya0 = fmaf(rr[j], vj0, ya0);
        ya1 = fmaf(rr[j + 1], vj1, ya1);
        yb0 = fmaf(rr[j], pj0, yb0);
        yb1 = fmaf(rr[j + 1], pj1, yb1);
    }
    double y1 = (double)(ya0 + ya1), y2 = (double)(yb0 + yb1);

    // ---- ONE fp64 refinement round, 4-way split accumulators ----
    {
        double a0 = 0, a1 = 0, a2 = 0, a3 = 0;
        double c0 = 0, c1 = 0, c2 = 0, c3 = 0;
#pragma unroll
        for (int j = 0; j < NSTEP; j += 4) {
            double u0 = __shfl_sync(FULL, y1, j);
            double u1 = __shfl_sync(FULL, y1, j + 1);
            double u2 = __shfl_sync(FULL, y1, j + 2);
            double u3 = __shfl_sync(FULL, y1, j + 3);
            double w0 = __shfl_sync(FULL, y2, j);
            double w1 = __shfl_sync(FULL, y2, j + 1);
            double w2 = __shfl_sync(FULL, y2, j + 2);
            double w3 = __shfl_sync(FULL, y2, j + 3);
            a0 += qrow[j] * u0;     a1 += qrow[j + 1] * u1;
            a2 += qrow[j + 2] * u2; a3 += qrow[j + 3] * u3;
            c0 += qrow[j] * w0;     c1 += qrow[j + 1] * w1;
            c2 += qrow[j + 2] * w2; c3 += qrow[j + 3] * w3;
        }
        double res1 = (double)v1 - ((a0 + a1) + (a2 + a3));
        double res2 = (double)p26 - ((c0 + c1) + (c2 + c3));
        double d0 = 0, d1 = 0, e0 = 0, e1 = 0;
#pragma unroll
        for (int j = 0; j < NSTEP; j += 2) {
            double r0 = __shfl_sync(FULL, res1, j);
            double r1 = __shfl_sync(FULL, res1, j + 1);
            double t0 = __shfl_sync(FULL, res2, j);
            double t1 = __shfl_sync(FULL, res2, j + 1);
            d0 += (double)rr[j] * r0;
            d1 += (double)rr[j + 1] * r1;
            e0 += (double)rr[j] * t0;
            e1 += (double)rr[j + 1] * t1;
        }
        y1 += d0 + d1;
        y2 += e0 + e1;
    }

    // ---- epilogue (fp32 triangular sums) ----
    float z1 = (float)y1, z2 = (float)y2;
    float a = 0, b = 0;
#pragma unroll
    for (int c = 0; c < NSTEP; c++) {
        float zc1 = __shfl_sync(FULL, z1, c);
        float zc2 = __shfl_sync(FULL, z2, c);
        if (c <= lane) {
            float ss = dt2f * (0.5f + (float)(lane - c));
            a = fmaf(ss, zc1, a);
            b = fmaf(ss, zc2, b);
        }
    }
    if (ls) {
        g_consts[NHID + lane]         = -a;
        g_consts[NHID + NSTEP + lane] = (float)(lane + 1) * dtf - b;
    }
    if (lh) g_consts[lane] = q0;
    // Implicit end-of-kernel PDL trigger releases the dependent grid.
}

// ---------------------------------------------------------------------------
// Main streaming kernel — UNCHANGED from round 14 (benched: 8.96us, correct;
// L2-resident working set across graph replays -> latency floor, leave it).
// ---------------------------------------------------------------------------
__global__ void __launch_bounds__(128) main_kernel(const float* __restrict__ x,
                                                   const float* __restrict__ gp,
                                                   const float* __restrict__ gv,
                                                   float* __restrict__ out) {
    __shared__ float sx[128 * NHID];      // 12.8 KB; warp w owns floats [w*800, w*800+800)
    __shared__ float strip[3 * 128];      // dp | p | v per row
    __shared__ float scw[4][80];          // per-warp consts
    const int t = threadIdx.x;
    const int w = t >> 5;
    const int lane = t & 31;
    const int base = blockIdx.x * 128;

    // Phase 1 (independent of setup): warp-local float4 stage of x rows.
    const float4* xb4 = (const float4*)(x + (size_t)base * NHID);
    float4* sx4 = (float4*)sx;
#pragma unroll
    for (int k = 0; k < 7; k++) {
        int i = k * 32 + lane;
        if (i < 200) {
            int idx = w * 200 + i;
            sx4[idx] = xb4[idx];
        }
    }
    const float p = gp[base + t];
    const float v = gv[base + t];

    // Gate on setup_kernel's g_consts (no-op when launched plain).
    cudaGridDependencySynchronize();

#pragma unroll
    for (int k = 0; k < 3; k++) {
        int i = k * 32 + lane;
        if (i < NHID + 2 * NSTEP) scw[w][i] = g_consts[i];
    }
    __syncwarp();

    float dp = 0.f;
#pragma unroll
    for (int i = 0; i < NHID; i++) dp = fmaf(sx[t * NHID + i], scw[w][i], dp);

    strip[t] = dp;
    strip[128 + t] = p;
    strip[256 + t] = v;
    __syncwarp();

    float4* ob4 = (float4*)(out + (size_t)base * NSTEP);
#pragma unroll
    for (int k = 0; k < 5; k++) {
        int j4 = w * 160 + k * 32 + lane;
        int j = 4 * j4;
        int r = j / NSTEP;
        int c = j - r * NSTEP;
        float dpr = strip[r];
        float pr  = strip[128 + r];
        float vr  = strip[256 + r];
        float4 vv;
        vv.x = fmaf(vr, scw[w][NHID + NSTEP + c    ], fmaf(dpr, scw[w][NHID + c    ], pr));
        vv.y = fmaf(vr, scw[w][NHID + NSTEP + c + 1], fmaf(dpr, scw[w][NHID + c + 1], pr));
        vv.z = fmaf(vr, scw[w][NHID + NSTEP + c + 2], fmaf(dpr, scw[w][NHID + c + 2], pr));
        vv.w = fmaf(vr, scw[w][NHID + NSTEP + c + 3], fmaf(dpr, scw[w][NHID + c + 3], pr));
        ob4[j4] = vv;
    }
}

extern "C" void kernel_launch(void* const* d_in, const int* in_sizes, int n_in,
                              void* d_out, int out_size) {
    const float* x  = (const float*)d_in[0];
    const float* gp = (const float*)d_in[1];
    const float* gv = (const float*)d_in[2];
    const float* Af = (const float*)d_in[3];
    const float* Lq = (const float*)d_in[4];
    float* out = (float*)d_out;

    const int nB = out_size / NSTEP;     // out is [B, NSTEP]

    setup_kernel<<<1, 32>>>(Af, Lq);

    // PDL: main's blocks start while setup runs; the grid-dependency sync
    // inside gates the g_consts read. Checked fallback to a plain launch.
    cudaLaunchConfig_t cfg = {};
    cfg.gridDim  = dim3((unsigned)(nB / 128), 1, 1);
    cfg.blockDim = dim3(128, 1, 1);
    cfg.dynamicSmemBytes = 0;
    cfg.stream = 0;
    cudaLaunchAttribute attr[1];
    attr[0].id = cudaLaunchAttributeProgrammaticStreamSerialization;
    attr[0].val.programmaticStreamSerializationAllowed = 1;
    cfg.attrs = attr;
    cfg.numAttrs = 1;
    cudaError_t err = cudaLaunchKernelEx(&cfg, main_kernel, x, gp, gv, out);
    if (err != cudaSuccess) {
        (void)cudaGetLastError();
        main_kernel<<<nB / 128, 128>>>(x, gp, gv, out);
    }
}